// round 9
// baseline (speedup 1.0000x reference)
#include <cuda_runtime.h>
#include <cuda_fp16.h>
#include <cstdint>
#include <cfloat>

// Problem constants
#define BATCH 256
#define CW    8192
#define NC    64
#define NS    4096
#define NE    128
#define BM    64             // batch rows per CTA (4 b-tiles)
#define BN    64             // dict entries per chunk
#define NCH   (NS / BN)      // 64 chunks
#define KS    8              // k-steps of 16
#define NTH   512

#define EMBED_ELEMS (BATCH * CW)
#define XSPITCH 132          // padded fp32 x row (bank-conflict-free refine)

// ---- smem layout (bytes) ----
#define SM_XF   0            // [8 ks][64 r][4 tg] uint2 = 16384
#define SM_BF   16384        // 2 x [8 ks][64 n][4 tg] uint2 = 32768
#define SM_XS   49152        // [64][132] fp32 = 33792
#define SM_DSQ  82944        // [2][64] float = 512
#define SM_WMIN 83456        // [8][64] float = 2048
#define SM_WIDX 85504        // [8][64] int   = 2048
#define SM_TOTAL 87552       // 2 CTAs/SM -> 175 KB

static __device__ __forceinline__ void mma_f16_f32(float4& c, uint32_t a0, uint32_t a1,
                                                   uint32_t a2, uint32_t a3,
                                                   uint32_t b0, uint32_t b1) {
    asm("mma.sync.aligned.m16n8k16.row.col.f32.f16.f16.f32 "
        "{%0,%1,%2,%3}, {%4,%5,%6,%7}, {%8,%9}, {%0,%1,%2,%3};"
        : "+f"(c.x), "+f"(c.y), "+f"(c.z), "+f"(c.w)
        : "r"(a0), "r"(a1), "r"(a2), "r"(a3), "r"(b0), "r"(b1));
}

static __device__ __forceinline__ uint32_t pack_h2(float f0, float f1) {
    __half2 h = __float22half2_rn(make_float2(f0, f1));
    return *(uint32_t*)&h;
}

// exact fp32 score = |d|^2 - 2 x.d  (x row from smem, dict row from gmem/L2)
static __device__ __forceinline__ float exact_score(const float* __restrict__ dictc,
                                                    const float* __restrict__ xsrow,
                                                    int idx) {
    const float4* dp = (const float4*)(dictc + (size_t)idx * NE);
    const float4* xp = (const float4*)xsrow;
    float dot = 0.f, ds = 0.f;
    #pragma unroll 8
    for (int j = 0; j < 32; ++j) {
        float4 d4 = dp[j];
        float4 x4 = xp[j];
        dot = fmaf(d4.x, x4.x, dot); ds = fmaf(d4.x, d4.x, ds);
        dot = fmaf(d4.y, x4.y, dot); ds = fmaf(d4.y, d4.y, ds);
        dot = fmaf(d4.z, x4.z, dot); ds = fmaf(d4.z, d4.z, ds);
        dot = fmaf(d4.w, x4.w, dot); ds = fmaf(d4.w, d4.w, ds);
    }
    return fmaf(-2.f, dot, ds);
}

// ====== fused kernel: approx hi*hi GEMM -> top2 -> exact rescore
// ======                + one-hot zeros + ones + embed gather
__global__ __launch_bounds__(NTH, 2)
void vq_fused(const float* __restrict__ x, const float* __restrict__ dict,
              float* __restrict__ out) {
    extern __shared__ char smem[];
    uint2* XF = (uint2*)(smem + SM_XF);
    uint2* BF = (uint2*)(smem + SM_BF);
    float* XS = (float*)(smem + SM_XS);
    float* dsq = (float*)(smem + SM_DSQ);
    float* wmin = (float*)(smem + SM_WMIN);
    int*   widx = (int*)(smem + SM_WIDX);

    const int tid  = threadIdx.x;
    const int wid  = tid >> 5;
    const int lane = tid & 31;
    const int gid  = lane >> 2;        // 0..7
    const int tg   = lane & 3;         // 0..3
    const int m0   = (wid & 1) * 32;   // 2 m-warps (32 rows each)
    const int nw   = wid >> 1;         // 0..7 (8 n-warps)
    const int n0   = nw * 8;           // n-warp origin (one n8 tile)

    const int c  = blockIdx.x;
    const int b0 = blockIdx.y * BM;

    // ---- fill XS (fp32) + XF (fp16 hi fragments): 8 threads per row ----
    {
        const int r   = tid >> 3;          // 0..63
        const int seg = tid & 7;           // 16-float k-step segment == ks
        const float* xr = x + (size_t)(b0 + r) * CW + (size_t)c * NE + seg * 16;
        float4 xv[4];
        #pragma unroll
        for (int j = 0; j < 4; ++j) xv[j] = *(const float4*)(xr + j * 4);
        float* xsrow = XS + r * XSPITCH + seg * 16;
        #pragma unroll
        for (int j = 0; j < 4; ++j) *(float4*)(xsrow + j * 4) = xv[j];
        const float* pf = (const float*)xv;
        #pragma unroll
        for (int t = 0; t < 4; ++t) {
            XF[seg * 256 + r * 4 + t] =
                make_uint2(pack_h2(pf[2 * t], pf[2 * t + 1]),
                           pack_h2(pf[2 * t + 8], pf[2 * t + 9]));
        }
    }

    // ---- per-thread state ----
    float4 acc[2];
    #pragma unroll
    for (int mt = 0; mt < 2; ++mt) acc[mt] = make_float4(0.f, 0.f, 0.f, 0.f);

    float b1[4], b2[4];
    int   x1[4], x2[4];
    #pragma unroll
    for (int i = 0; i < 4; ++i) { b1[i] = FLT_MAX; b2[i] = FLT_MAX; x1[i] = 0; x2[i] = 0; }

    // dict conversion role: 8 threads per dict row (16-col segment = one ks)
    const int dn   = tid >> 3;             // 0..63
    const int tseg = tid & 7;              // 0..7 == ks
    const float* dbase = dict + (size_t)c * NS * NE + tseg * 16;

    // one-hot zero-fill role: 64 rows x 64 floats per chunk; 8 thr/row, 8 floats each
    const int zr = tid >> 3;               // 0..63
    const int zc = (tid & 7) * 8;          // 0..56

    float4 pre[4];
    {   // prefetch chunk 0 (16 floats per thread)
        const float* src = dbase + (size_t)dn * NE;
        #pragma unroll
        for (int j = 0; j < 4; ++j) pre[j] = *(const float4*)(src + j * 4);
    }

    // convert chunk 0 into buffer 0
    {
        const float* pf = (const float*)pre;
        float ss = 0.f;
        #pragma unroll
        for (int i = 0; i < 16; ++i) ss = fmaf(pf[i], pf[i], ss);
        #pragma unroll
        for (int t = 0; t < 4; ++t) {
            BF[tseg * 256 + dn * 4 + t] =
                make_uint2(pack_h2(pf[2 * t], pf[2 * t + 1]),
                           pack_h2(pf[2 * t + 8], pf[2 * t + 9]));
        }
        ss += __shfl_xor_sync(0xffffffffu, ss, 1);
        ss += __shfl_xor_sync(0xffffffffu, ss, 2);
        ss += __shfl_xor_sync(0xffffffffu, ss, 4);
        if (tseg == 0) dsq[dn] = ss;
    }
    __syncthreads();

    for (int s = 0; s < NCH; ++s) {
        const int p = s & 1;
        const uint2* BFp = BF + p * 2048;

        // ---- prefetch next chunk ----
        if (s + 1 < NCH) {
            const float* src = dbase + (size_t)((s + 1) * BN + dn) * NE;
            #pragma unroll
            for (int j = 0; j < 4; ++j) pre[j] = *(const float4*)(src + j * 4);
        }

        // ---- one-hot zero-fill: segment s of the 64 owned rows ----
        {
            float4* dst = (float4*)(out + (size_t)EMBED_ELEMS +
                                    ((size_t)(b0 + zr) * NC + c) * NS + (size_t)s * BN + zc);
            __stwt(dst, make_float4(0.f, 0.f, 0.f, 0.f));
            __stwt(dst + 1, make_float4(0.f, 0.f, 0.f, 0.f));
        }

        // ---- mma phase: 8 ks x (2m x 1n) single hi*hi pass ----
        #pragma unroll
        for (int ks = 0; ks < KS; ++ks) {
            uint2 A0[2], A1[2], Bv;
            #pragma unroll
            for (int mt = 0; mt < 2; ++mt) {
                A0[mt] = XF[ks * 256 + (m0 + mt * 16 + gid) * 4 + tg];
                A1[mt] = XF[ks * 256 + (m0 + mt * 16 + 8 + gid) * 4 + tg];
            }
            Bv = BFp[ks * 256 + (n0 + gid) * 4 + tg];

            #pragma unroll
            for (int mt = 0; mt < 2; ++mt)
                mma_f16_f32(acc[mt], A0[mt].x, A1[mt].x, A0[mt].y, A1[mt].y,
                            Bv.x, Bv.y);
        }

        // ---- convert chunk s+1 into other buffer ----
        if (s + 1 < NCH) {
            const int q = (s + 1) & 1;
            uint2* BFq = BF + q * 2048;
            const float* pf = (const float*)pre;
            float ss = 0.f;
            #pragma unroll
            for (int i = 0; i < 16; ++i) ss = fmaf(pf[i], pf[i], ss);
            #pragma unroll
            for (int t = 0; t < 4; ++t) {
                BFq[tseg * 256 + dn * 4 + t] =
                    make_uint2(pack_h2(pf[2 * t], pf[2 * t + 1]),
                               pack_h2(pf[2 * t + 8], pf[2 * t + 9]));
            }
            ss += __shfl_xor_sync(0xffffffffu, ss, 1);
            ss += __shfl_xor_sync(0xffffffffu, ss, 2);
            ss += __shfl_xor_sync(0xffffffffu, ss, 4);
            if (tseg == 0) dsq[q * 64 + dn] = ss;
        }

        // ---- epilogue: approx scores -> top-2 per slot, reset accs ----
        const int sbase = s * BN;
        #pragma unroll
        for (int mt = 0; mt < 2; ++mt) {
            const int colb = n0 + 2 * tg;
            const float d0 = dsq[p * 64 + colb];
            const float d1 = dsq[p * 64 + colb + 1];
            float4 hh = acc[mt];
            const int i0 = sbase + colb;
            #pragma unroll
            for (int rh = 0; rh < 2; ++rh) {      // row gid / gid+8
                const int sl = mt * 2 + rh;
                const float sA = fmaf(-2.f, rh ? hh.z : hh.x, d0);
                const float sB = fmaf(-2.f, rh ? hh.w : hh.y, d1);
                if (sA < b1[sl]) { b2[sl] = b1[sl]; x2[sl] = x1[sl]; b1[sl] = sA; x1[sl] = i0; }
                else if (sA < b2[sl]) { b2[sl] = sA; x2[sl] = i0; }
                if (sB < b1[sl]) { b2[sl] = b1[sl]; x2[sl] = x1[sl]; b1[sl] = sB; x1[sl] = i0 + 1; }
                else if (sB < b2[sl]) { b2[sl] = sB; x2[sl] = i0 + 1; }
            }
            acc[mt] = make_float4(0.f, 0.f, 0.f, 0.f);
        }
        __syncthreads();   // BF buffer handoff
    }

    // ---- exact rescore of the 2 candidates per slot, reduce per row ----
    const float* dictc = dict + (size_t)c * NS * NE;
    #pragma unroll
    for (int slot = 0; slot < 4; ++slot) {
        const int r = m0 + (slot >> 1) * 16 + (slot & 1) * 8 + gid;
        const float* xsrow = XS + r * XSPITCH;
        const int ia = x1[slot], ib = x2[slot];
        float ea = exact_score(dictc, xsrow, ia);
        float eb = exact_score(dictc, xsrow, ib);
        float v; int ix;
        if (ea < eb || (ea == eb && ia < ib)) { v = ea; ix = ia; }
        else { v = eb; ix = ib; }
        #pragma unroll
        for (int off = 1; off <= 2; off <<= 1) {
            float ov = __shfl_xor_sync(0xffffffffu, v, off);
            int   oi = __shfl_xor_sync(0xffffffffu, ix, off);
            if (ov < v || (ov == v && oi < ix)) { v = ov; ix = oi; }
        }
        if (tg == 0) {
            wmin[nw * 64 + r] = v;
            widx[nw * 64 + r] = ix;
        }
    }
    __syncthreads();

    // ---- final per-row winner across the 8 n-warps: 1.0 + stash ----
    if (tid < 64) {
        float v = wmin[tid];
        int  ix = widx[tid];
        #pragma unroll
        for (int k = 1; k < 8; ++k) {
            const float ov = wmin[k * 64 + tid];
            const int   oi = widx[k * 64 + tid];
            if (ov < v || (ov == v && oi < ix)) { v = ov; ix = oi; }
        }
        out[(size_t)EMBED_ELEMS + ((size_t)(b0 + tid) * NC + c) * NS + ix] = 1.0f;
        widx[tid] = ix;
    }
    __syncthreads();

    // ---- gather nearest codewords into the embed region (8 threads / row) ----
    {
        const int r  = tid >> 3;
        const int qr = tid & 7;
        const int ix = widx[r];
        const float4* src = (const float4*)(dictc + (size_t)ix * NE) + qr * 4;
        float4* dst = (float4*)(out + (size_t)(b0 + r) * CW + c * NE) + qr * 4;
        #pragma unroll
        for (int j = 0; j < 4; ++j) __stwt(&dst[j], src[j]);
    }
}

extern "C" void kernel_launch(void* const* d_in, const int* in_sizes, int n_in,
                              void* d_out, int out_size) {
    const float* x    = (const float*)d_in[0];   // [256, 8192]
    const float* dict = (const float*)d_in[1];   // [64, 4096, 128]
    float* out = (float*)d_out;

    cudaFuncSetAttribute(vq_fused,
                         cudaFuncAttributeMaxDynamicSharedMemorySize, SM_TOTAL);

    vq_fused<<<dim3(NC, BATCH / BM), NTH, SM_TOTAL>>>(x, dict, out);
}

// round 11
// speedup vs baseline: 2.1146x; 2.1146x over previous
#include <cuda_runtime.h>
#include <cuda_fp16.h>
#include <cstdint>
#include <cfloat>

// Problem constants
#define BATCH 256
#define CW    8192
#define NC    64
#define NS    4096
#define NE    128
#define BM    128
#define BN    64
#define NCH   (NS / BN)      // 64 chunks
#define KS    8
#define NTH   512
#define EMBED_ELEMS (BATCH * CW)
#define XSPITCH 132
#define DELTA 0.5f

// ---- smem layout (bytes) ----
#define SM_XF   0            // [8 ks][8 m16][32 lane] uint4 = 32768 (aliased by cand after loop)
#define SM_BF   32768        // 2 x [8 ks][4 pair][32 lane] uint4 = 32768
#define SM_XS   65536        // [128][132] fp32 = 67584
#define SM_DSQ  133120       // [2][64] float = 512
#define SM_WIDXF 133632      // [128] int = 512
#define SM_TOTAL 134144

static __device__ __forceinline__ void mma_f16_f32(float4& c, uint32_t a0, uint32_t a1,
                                                   uint32_t a2, uint32_t a3,
                                                   uint32_t b0, uint32_t b1) {
    asm("mma.sync.aligned.m16n8k16.row.col.f32.f16.f16.f32 "
        "{%0,%1,%2,%3}, {%4,%5,%6,%7}, {%8,%9}, {%0,%1,%2,%3};"
        : "+f"(c.x), "+f"(c.y), "+f"(c.z), "+f"(c.w)
        : "r"(a0), "r"(a1), "r"(a2), "r"(a3), "r"(b0), "r"(b1));
}

static __device__ __forceinline__ uint32_t pack_h2(float f0, float f1) {
    __half2 h = __float22half2_rn(make_float2(f0, f1));
    return *(uint32_t*)&h;
}

__global__ __launch_bounds__(NTH, 1)
void vq_fused(const float* __restrict__ x, const float* __restrict__ dict,
              float* __restrict__ out) {
    extern __shared__ char smem[];
    uint4* XF = (uint4*)(smem + SM_XF);          // [ks][m16][lane]
    float* XS = (float*)(smem + SM_XS);
    float* dsq = (float*)(smem + SM_DSQ);
    int*   widxf = (int*)(smem + SM_WIDXF);
    // aliased over XF after the main loop:
    float* cand_s = (float*)(smem + SM_XF);       // [128][32]
    int*   cand_i = (int*)(smem + SM_XF + 16384); // [128][32]

    const int tid  = threadIdx.x;
    const int wid  = tid >> 5;
    const int lane = tid & 31;
    const int gid  = lane >> 2;
    const int tg   = lane & 3;
    const int mw   = wid & 3;          // 4 m-warps (32 rows each)
    const int nw2  = wid >> 2;         // 4 n-warps (16 cols each)

    const int c  = blockIdx.x;
    const int b0 = blockIdx.y * BM;

    // ---- 1. XS fill (coalesced fp32 x tile) ----
    {
        const int r = tid >> 2;
        const int q = tid & 3;
        const float* xr = x + (size_t)(b0 + r) * CW + (size_t)c * NE + q * 32;
        float* xsrow = XS + r * XSPITCH + q * 32;
        #pragma unroll
        for (int j = 0; j < 8; ++j)
            *(float4*)(xsrow + j * 4) = *(const float4*)(xr + j * 4);
    }

    // dict conversion role: thread (dn, ksg) handles 16 contiguous floats of one row
    const int dn  = tid >> 3;              // 0..63
    const int ksg = tid & 7;               // 0..7 == ks
    const float* dbase = dict + (size_t)c * NS * NE + ksg * 16;

    float4 pre[4];
    {   // prefetch chunk 0 (independent of XS fill)
        const float* src = dbase + (size_t)dn * NE;
        #pragma unroll
        for (int j = 0; j < 4; ++j) pre[j] = *(const float4*)(src + j * 4);
    }
    __syncthreads();   // XS ready

    // ---- 2. XF build from XS: full A-frag (uint4) per (ks, m16, lane) ----
    #pragma unroll
    for (int e = 0; e < 4; ++e) {
        const int idx = tid + e * NTH;          // 0..2047
        const int ks  = idx >> 8;
        const int M   = (idx >> 5) & 7;
        const int ln  = idx & 31;
        const int g   = ln >> 2, t = ln & 3;
        const int r0  = M * 16 + g;
        const int kb  = ks * 16 + 2 * t;
        float2 f0 = *(const float2*)&XS[r0 * XSPITCH + kb];
        float2 f1 = *(const float2*)&XS[(r0 + 8) * XSPITCH + kb];
        float2 f2 = *(const float2*)&XS[r0 * XSPITCH + kb + 8];
        float2 f3 = *(const float2*)&XS[(r0 + 8) * XSPITCH + kb + 8];
        XF[idx] = make_uint4(pack_h2(f0.x, f0.y), pack_h2(f1.x, f1.y),
                             pack_h2(f2.x, f2.y), pack_h2(f3.x, f3.y));
    }

    // ---- convert chunk 0 into BF buffer 0 ----
    {
        const float* pf = (const float*)pre;
        float ss = 0.f;
        #pragma unroll
        for (int i = 0; i < 16; ++i) ss = fmaf(pf[i], pf[i], ss);
        const int p = dn >> 4, g = dn & 7, hf = (dn >> 3) & 1;
        char* bptr = smem + SM_BF + ksg * 2048 + p * 512 + hf * 8;
        #pragma unroll
        for (int t = 0; t < 4; ++t) {
            uint2 v = make_uint2(pack_h2(pf[2 * t], pf[2 * t + 1]),
                                 pack_h2(pf[8 + 2 * t], pf[8 + 2 * t + 1]));
            *(uint2*)(bptr + (g * 4 + t) * 16) = v;
        }
        ss += __shfl_xor_sync(0xffffffffu, ss, 1);
        ss += __shfl_xor_sync(0xffffffffu, ss, 2);
        ss += __shfl_xor_sync(0xffffffffu, ss, 4);
        if (ksg == 0) dsq[dn] = ss;
    }

    // ---- per-thread state ----
    float4 acc[2][2];
    #pragma unroll
    for (int mt = 0; mt < 2; ++mt)
        #pragma unroll
        for (int nt = 0; nt < 2; ++nt) acc[mt][nt] = make_float4(0.f, 0.f, 0.f, 0.f);

    float b1[4], b2[4];
    int   x1[4], x2[4];
    #pragma unroll
    for (int i = 0; i < 4; ++i) { b1[i] = FLT_MAX; b2[i] = FLT_MAX; x1[i] = 0; x2[i] = 0; }

    // zero-fill role: coalesced 64B-per-4-lane groups
    const int zr = tid >> 2;               // 0..127
    const int zj = tid & 3;
    __syncthreads();

    const int colA = nw2 * 16 + 2 * tg;    // n8-tile 0 of this n-warp

    for (int s = 0; s < NCH; ++s) {
        const int p = s & 1;
        const char* BFp = smem + SM_BF + p * 16384;

        // ---- prefetch next chunk ----
        if (s + 1 < NCH) {
            const float* src = dbase + (size_t)((s + 1) * BN + dn) * NE;
            #pragma unroll
            for (int j = 0; j < 4; ++j) pre[j] = *(const float4*)(src + j * 4);
        }

        // ---- one-hot zero-fill: segment s, coalesced ----
        {
            float4* dst = (float4*)(out + (size_t)EMBED_ELEMS +
                                    ((size_t)(b0 + zr) * NC + c) * NS + (size_t)s * BN);
            #pragma unroll
            for (int j = 0; j < 4; ++j)
                __stwt(&dst[zj + 4 * j], make_float4(0.f, 0.f, 0.f, 0.f));
        }

        // ---- mma phase: 8 ks x (2 A LDS.128 + 1 B LDS.128 + 4 HMMA) ----
        #pragma unroll
        for (int ks = 0; ks < KS; ++ks) {
            uint4 A0 = XF[ks * 256 + (mw * 2) * 32 + lane];
            uint4 A1 = XF[ks * 256 + (mw * 2 + 1) * 32 + lane];
            uint4 Bv = *(const uint4*)(BFp + ks * 2048 + nw2 * 512 + lane * 16);
            mma_f16_f32(acc[0][0], A0.x, A0.y, A0.z, A0.w, Bv.x, Bv.y);
            mma_f16_f32(acc[0][1], A0.x, A0.y, A0.z, A0.w, Bv.z, Bv.w);
            mma_f16_f32(acc[1][0], A1.x, A1.y, A1.z, A1.w, Bv.x, Bv.y);
            mma_f16_f32(acc[1][1], A1.x, A1.y, A1.z, A1.w, Bv.z, Bv.w);
        }

        // ---- convert chunk s+1 into other buffer ----
        if (s + 1 < NCH) {
            const float* pf = (const float*)pre;
            float ss = 0.f;
            #pragma unroll
            for (int i = 0; i < 16; ++i) ss = fmaf(pf[i], pf[i], ss);
            const int pp = dn >> 4, g = dn & 7, hf = (dn >> 3) & 1;
            char* bptr = smem + SM_BF + (p ^ 1) * 16384 + ksg * 2048 + pp * 512 + hf * 8;
            #pragma unroll
            for (int t = 0; t < 4; ++t) {
                uint2 v = make_uint2(pack_h2(pf[2 * t], pf[2 * t + 1]),
                                     pack_h2(pf[8 + 2 * t], pf[8 + 2 * t + 1]));
                *(uint2*)(bptr + (g * 4 + t) * 16) = v;
            }
            ss += __shfl_xor_sync(0xffffffffu, ss, 1);
            ss += __shfl_xor_sync(0xffffffffu, ss, 2);
            ss += __shfl_xor_sync(0xffffffffu, ss, 4);
            if (ksg == 0) dsq[(p ^ 1) * 64 + dn] = ss;
        }

        // ---- epilogue: min-of-4 + rare top-2 insert, then RESET accs ----
        {
            const float dA0 = dsq[p * 64 + colA];
            const float dA1 = dsq[p * 64 + colA + 1];
            const float dB0 = dsq[p * 64 + colA + 8];
            const float dB1 = dsq[p * 64 + colA + 9];
            const int base = s * BN + colA;
            #pragma unroll
            for (int mt = 0; mt < 2; ++mt) {
                #pragma unroll
                for (int h = 0; h < 2; ++h) {
                    const int sl = mt * 2 + h;
                    const float s0 = fmaf(-2.f, h ? acc[mt][0].z : acc[mt][0].x, dA0);
                    const float s1 = fmaf(-2.f, h ? acc[mt][0].w : acc[mt][0].y, dA1);
                    const float s2 = fmaf(-2.f, h ? acc[mt][1].z : acc[mt][1].x, dB0);
                    const float s3 = fmaf(-2.f, h ? acc[mt][1].w : acc[mt][1].y, dB1);
                    const float m1 = fminf(fminf(s0, s1), fminf(s2, s3));
                    if (m1 < b2[sl]) {
                        const float mn01 = fminf(s0, s1), mx01 = fmaxf(s0, s1);
                        const float mn23 = fminf(s2, s3), mx23 = fmaxf(s2, s3);
                        const float m2 = fminf(fminf(mx01, mx23), fmaxf(mn01, mn23));
                        const int p1 = (m1 == s0) ? 0 : (m1 == s1) ? 1 : (m1 == s2) ? 2 : 3;
                        const int i1 = base + (p1 & 1) + (p1 >> 1) * 8;
                        if (m1 < b1[sl]) { b2[sl] = b1[sl]; x2[sl] = x1[sl]; b1[sl] = m1; x1[sl] = i1; }
                        else             { b2[sl] = m1; x2[sl] = i1; }
                        if (m2 < b2[sl]) {
                            int p2;
                            if (m2 == s0 && p1 != 0) p2 = 0;
                            else if (m2 == s1 && p1 != 1) p2 = 1;
                            else if (m2 == s2 && p1 != 2) p2 = 2;
                            else p2 = 3;
                            b2[sl] = m2;
                            x2[sl] = base + (p2 & 1) + (p2 >> 1) * 8;
                        }
                    }
                }
            }
            // reset accumulators for the next chunk (THE R10 BUG was omitting this)
            #pragma unroll
            for (int mt = 0; mt < 2; ++mt)
                #pragma unroll
                for (int nt = 0; nt < 2; ++nt)
                    acc[mt][nt] = make_float4(0.f, 0.f, 0.f, 0.f);
        }
        __syncthreads();   // BF/dsq buffer handoff
    }

    // ---- stage 1: dump candidates to smem (aliases XF, safe after barrier) ----
    {
        const int slotid = nw2 * 4 + tg;
        #pragma unroll
        for (int sl = 0; sl < 4; ++sl) {
            const int R = mw * 32 + (sl >> 1) * 16 + (sl & 1) * 8 + gid;
            cand_s[R * 32 + slotid * 2]     = b1[sl];
            cand_s[R * 32 + slotid * 2 + 1] = b2[sl];
            cand_i[R * 32 + slotid * 2]     = x1[sl];
            cand_i[R * 32 + slotid * 2 + 1] = x2[sl];
        }
    }
    __syncthreads();

    // ---- stage 2: warp-per-row exact rescore of near-min candidates ----
    const float* dictc = dict + (size_t)c * NS * NE;
    for (int rr = 0; rr < 8; ++rr) {
        const int r = wid * 8 + rr;
        float sc = cand_s[r * 32 + lane];
        int   ix = cand_i[r * 32 + lane];
        float m = sc;
        #pragma unroll
        for (int off = 16; off; off >>= 1)
            m = fminf(m, __shfl_xor_sync(0xffffffffu, m, off));
        float es = FLT_MAX;
        if (sc <= m + DELTA) {
            const float4* dp = (const float4*)(dictc + (size_t)ix * NE);
            const float4* xp = (const float4*)(XS + r * XSPITCH);
            float dot = 0.f, ds2 = 0.f;
            #pragma unroll 8
            for (int j = 0; j < 32; ++j) {
                const float4 d4 = __ldg(&dp[j]);
                const float4 x4 = xp[j];
                dot = fmaf(d4.x, x4.x, dot); ds2 = fmaf(d4.x, d4.x, ds2);
                dot = fmaf(d4.y, x4.y, dot); ds2 = fmaf(d4.y, d4.y, ds2);
                dot = fmaf(d4.z, x4.z, dot); ds2 = fmaf(d4.z, d4.z, ds2);
                dot = fmaf(d4.w, x4.w, dot); ds2 = fmaf(d4.w, d4.w, ds2);
            }
            es = fmaf(-2.f, dot, ds2);
        }
        #pragma unroll
        for (int off = 16; off; off >>= 1) {
            const float oe = __shfl_xor_sync(0xffffffffu, es, off);
            const int   oi = __shfl_xor_sync(0xffffffffu, ix, off);
            if (oe < es || (oe == es && oi < ix)) { es = oe; ix = oi; }
        }
        if (lane == 0) {
            out[(size_t)EMBED_ELEMS + ((size_t)(b0 + r) * NC + c) * NS + ix] = 1.0f;
            widxf[r] = ix;
        }
    }
    __syncthreads();

    // ---- stage 3: gather nearest codewords into the embed region ----
    {
        const int r = tid >> 2;
        const int q = tid & 3;
        const int ix = widxf[r];
        const float4* src = (const float4*)(dictc + (size_t)ix * NE) + q * 8;
        float4* dst = (float4*)(out + (size_t)(b0 + r) * CW + c * NE) + q * 8;
        #pragma unroll
        for (int j = 0; j < 8; ++j) __stwt(&dst[j], src[j]);
    }
}

extern "C" void kernel_launch(void* const* d_in, const int* in_sizes, int n_in,
                              void* d_out, int out_size) {
    const float* x    = (const float*)d_in[0];   // [256, 8192]
    const float* dict = (const float*)d_in[1];   // [64, 4096, 128]
    float* out = (float*)d_out;

    cudaFuncSetAttribute(vq_fused,
                         cudaFuncAttributeMaxDynamicSharedMemorySize, SM_TOTAL);

    vq_fused<<<dim3(NC, BATCH / BM), NTH, SM_TOTAL>>>(x, dict, out);
}